// round 13
// baseline (speedup 1.0000x reference)
#include <cuda_runtime.h>
#include <cuda_fp16.h>
#include <math.h>
#include <stdint.h>

// ---------------- problem constants ----------------
#define BB 32
#define SS 512
#define DM 512
#define NH 8
#define DK 64
#define DINNER 2048
#define MTOT (BB * SS)              // 16384 rows
#define ENC_ELEMS (BB * SS * DM)    // 8388608
#define EPSLN 1e-3f

// ---------------- scratch (device globals; no allocation allowed) ----------------
__device__ __half g_xch[MTOT * DM];         // compacted input fp16 (GEMM A + LN1 residual)
__device__ __half g_qkvh[MTOT * 3 * DM];    // merged q|k|v  [row][1536] fp16
__device__ __half g_headsh[MTOT * DM];      // attn heads (fp16)
__device__ __half g_tmph[MTOT * DM];        // pre-LN gemm out (fp16, reused)
__device__ __half g_attnouth[MTOT * DM];    // LN1 output (fp16)
__device__ __half g_ffnh[MTOT * DINNER];    // FFN hidden (fp16, relu'd)
__device__ __half g_wqkvT[1536 * DM];       // [n][k] fp16
__device__ __half g_projwT[DM * DM];
__device__ __half g_w1T[DINNER * DM];
__device__ __half g_w2T[DM * DINNER];
__device__ int    g_idx[BB * SS];
__device__ int    g_nkeep[BB];

// ---------------- helpers ----------------
__device__ __forceinline__ void cpa16(uint32_t dst, const void* src) {
    asm volatile("cp.async.cg.shared.global [%0], [%1], 16;" :: "r"(dst), "l"(src));
}
__device__ __forceinline__ void ldm_x4(uint32_t* r, uint32_t addr) {
    asm volatile("ldmatrix.sync.aligned.m8n8.x4.shared.b16 {%0,%1,%2,%3}, [%4];"
                 : "=r"(r[0]), "=r"(r[1]), "=r"(r[2]), "=r"(r[3]) : "r"(addr));
}
__device__ __forceinline__ void ldm_x4_t(uint32_t* r, uint32_t addr) {
    asm volatile("ldmatrix.sync.aligned.m8n8.x4.trans.shared.b16 {%0,%1,%2,%3}, [%4];"
                 : "=r"(r[0]), "=r"(r[1]), "=r"(r[2]), "=r"(r[3]) : "r"(addr));
}
__device__ __forceinline__ void mma_f16(float* d, const uint32_t* a, uint32_t b0, uint32_t b1) {
    asm volatile(
        "mma.sync.aligned.m16n8k16.row.col.f32.f16.f16.f32 "
        "{%0,%1,%2,%3}, {%4,%5,%6,%7}, {%8,%9}, {%0,%1,%2,%3};"
        : "+f"(d[0]), "+f"(d[1]), "+f"(d[2]), "+f"(d[3])
        : "r"(a[0]), "r"(a[1]), "r"(a[2]), "r"(a[3]), "r"(b0), "r"(b1));
}
__device__ __forceinline__ float fast_exp(float x) {
    float t = x * 1.4426950408889634f;
    float z = t + 12582912.0f;
    int   m = __float_as_int(z) - 0x4B400000;
    float f = t - (z - 12582912.0f);
    float p = 1.3333558146e-3f;
    p = fmaf(p, f, 9.6181291076e-3f);
    p = fmaf(p, f, 5.5504108665e-2f);
    p = fmaf(p, f, 2.4022650696e-1f);
    p = fmaf(p, f, 6.9314718056e-1f);
    p = fmaf(p, f, 1.0f);
    return __int_as_float(__float_as_int(p) + (m << 23));
}
__device__ __forceinline__ uint32_t smem_u32(const void* p) {
    uint32_t a;
    asm("{ .reg .u64 t; cvta.to.shared.u64 t, %1; cvt.u32.u64 %0, t; }" : "=r"(a) : "l"(p));
    return a;
}
__device__ __forceinline__ void stcs4(float* p, float4 v) {
    asm volatile("st.global.cs.v4.f32 [%0], {%1,%2,%3,%4};"
                 :: "l"(p), "f"(v.x), "f"(v.y), "f"(v.z), "f"(v.w) : "memory");
}

// ---------------- weight prep: 3 transposes + qkv pack in ONE launch ----------------
__global__ void prep_all(const float* __restrict__ proj_w, const float* __restrict__ w1,
                         const float* __restrict__ w2, const float* __restrict__ wq,
                         const float* __restrict__ wk, const float* __restrict__ wv,
                         __half* __restrict__ projwT, __half* __restrict__ w1T,
                         __half* __restrict__ w2T, __half* __restrict__ wqkvT) {
    int z = blockIdx.z;
    int tx = threadIdx.x, ty = threadIdx.y;  // 32 x 8
    if (z == 3) {
        int lb = blockIdx.y * 64 + blockIdx.x;
        if (lb >= 3072) return;
        int i = lb * 256 + ty * 32 + tx;
        int n = i >> 9;
        int d = i & 511;
        int sel = n >> 9;
        int nn = n & 511;
        int h = nn >> 6, kk = nn & 63;
        const float* w = (sel == 0) ? wq : (sel == 1) ? wk : wv;
        wqkvT[i] = __float2half_rn(w[(h * DM + d) * DK + kk]);
        return;
    }
    __shared__ float t[32][33];
    const float* in;
    __half* out;
    int R, C;
    if (z == 0)      { in = proj_w; out = projwT; R = DM;     C = DM; }
    else if (z == 1) { in = w1;     out = w1T;    R = DM;     C = DINNER; }
    else             { in = w2;     out = w2T;    R = DINNER; C = DM; }
    int c0 = blockIdx.x * 32, r0 = blockIdx.y * 32;
    if (c0 >= C || r0 >= R) return;
#pragma unroll
    for (int j = 0; j < 32; j += 8)
        t[ty + j][tx] = in[(size_t)(r0 + ty + j) * C + c0 + tx];
    __syncthreads();
#pragma unroll
    for (int j = 0; j < 32; j += 8)
        out[(size_t)(c0 + ty + j) * R + r0 + tx] = __float2half_rn(t[tx][ty + j]);
}

// ---------------- skipper ----------------
__global__ void skipper_scan(const int* __restrict__ keep, int* __restrict__ idx,
                             int* __restrict__ nkeep) {
    int b = blockIdx.x, t = threadIdx.x;
    __shared__ int sh[SS];
    int v = keep[b * SS + t] > 0;
    sh[t] = v;
    __syncthreads();
    for (int off = 1; off < SS; off <<= 1) {
        int x = (t >= off) ? sh[t - off] : 0;
        __syncthreads();
        sh[t] += x;
        __syncthreads();
    }
    int incl = sh[t];
    if (v) idx[b * SS + incl - 1] = t;
    if (t == SS - 1) nkeep[b] = incl;
}

// 2 rows per 256-thread block
__global__ void gather_kernel(const float* __restrict__ x, const int* __restrict__ idx,
                              const int* __restrict__ nkeep, __half* __restrict__ xch) {
    int bs = blockIdx.x * 2 + (threadIdx.x >> 7);
    int t = threadIdx.x & 127;
    int b = bs >> 9, s = bs & 511;
    int nk = nkeep[b];
    float4 v = make_float4(0.f, 0.f, 0.f, 0.f);
    if (s < nk)
        v = ((const float4*)(x + ((size_t)b * SS + idx[b * SS + s]) * DM))[t];
    __half2 h0 = __floats2half2_rn(v.x, v.y);
    __half2 h1 = __floats2half2_rn(v.z, v.w);
    uint2 u;
    u.x = *(uint32_t*)&h0;
    u.y = *(uint32_t*)&h1;
    ((uint2*)(xch + (size_t)bs * DM))[t] = u;
}

// ---------------- fp16 tensor-core GEMM (128x256 block, 64x64 warp tile, 3-stage) -----
// A bufs: 3 x 16KB at 0; B bufs: 3 x 32KB at 49152. Total 147456 B.
#define HSM_TOTAL 147456

__global__ void __launch_bounds__(256, 1) hgemm(
    const __half* __restrict__ A, const __half* __restrict__ Bt,
    float* __restrict__ Cf, __half* __restrict__ Ch,
    int M, int N, int K, const float* __restrict__ bias, int relu) {
    extern __shared__ __align__(128) char smc[];
    uint32_t sbase = smem_u32(smc);

    int tid = threadIdx.x;
    int wid = tid >> 5, lane = tid & 31;
    int g = lane >> 2, t4 = lane & 3;
    int l15 = lane & 15, l16 = lane >> 4;
    int wm = wid >> 2, wn = wid & 3;      // 2 x 4 warps, warp tile 64x64
    int rowBase = blockIdx.y * 128;
    int colBase = blockIdx.x * 256;

    float acc[4][8][4];
#pragma unroll
    for (int i = 0; i < 4; i++)
#pragma unroll
        for (int j = 0; j < 8; j++)
#pragma unroll
            for (int c = 0; c < 4; c++) acc[i][j][c] = 0.f;

    const int nc = K / 64;

    auto load_tile = [&](int kt, int buf) {
        int k0 = kt * 64;
        // A: 128 rows x 128B = 1024 chunks (4 per thread)
#pragma unroll
        for (int j = 0; j < 4; j++) {
            int cid = tid + 256 * j;
            int row = cid >> 3, c = cid & 7;
            uint32_t off = row * 128 + ((c ^ (row & 7)) << 4);
            cpa16(sbase + buf * 16384 + off,
                  A + (size_t)(rowBase + row) * K + k0 + c * 8);
        }
        // B: 256 rows x 128B = 2048 chunks (8 per thread)
#pragma unroll
        for (int j = 0; j < 8; j++) {
            int cid = tid + 256 * j;
            int row = cid >> 3, c = cid & 7;
            uint32_t off = row * 128 + ((c ^ (row & 7)) << 4);
            cpa16(sbase + 49152 + buf * 32768 + off,
                  Bt + (size_t)(colBase + row) * K + k0 + c * 8);
        }
        asm volatile("cp.async.commit_group;");
    };

    load_tile(0, 0);
    if (nc > 1) load_tile(1, 1);
    asm volatile("cp.async.wait_group %0;" :: "n"(1));
    __syncthreads();

    for (int kt = 0; kt < nc; kt++) {
        int buf = kt % 3;
        if (kt + 2 < nc) load_tile(kt + 2, (kt + 2) % 3);

        uint32_t aBase = sbase + buf * 16384;
        uint32_t bBase = sbase + 49152 + buf * 32768;
#pragma unroll
        for (int ks = 0; ks < 4; ks++) {
            int ch = 2 * ks + l16;
            uint32_t a[4][4];
#pragma unroll
            for (int mt = 0; mt < 4; mt++) {
                int row = wm * 64 + mt * 16 + l15;
                ldm_x4(a[mt], aBase + row * 128 + ((ch ^ (row & 7)) << 4));
            }
            uint32_t bq[4][4];
#pragma unroll
            for (int bt = 0; bt < 4; bt++) {
                int row = wn * 64 + bt * 16 + l15;
                ldm_x4(bq[bt], bBase + row * 128 + ((ch ^ (row & 7)) << 4));
            }
#pragma unroll
            for (int mt = 0; mt < 4; mt++)
#pragma unroll
                for (int nt = 0; nt < 8; nt++)
                    mma_f16(acc[mt][nt], a[mt], bq[nt >> 1][nt & 1], bq[nt >> 1][2 + (nt & 1)]);
        }

        if (kt + 1 < nc) {
            if (kt + 2 < nc) {
                asm volatile("cp.async.wait_group %0;" :: "n"(1));
            } else {
                asm volatile("cp.async.wait_group 0;");
            }
            __syncthreads();
        }
    }

#pragma unroll
    for (int mt = 0; mt < 4; mt++) {
        int r0 = rowBase + wm * 64 + mt * 16 + g;
#pragma unroll
        for (int nt = 0; nt < 8; nt++) {
            int c = colBase + wn * 64 + nt * 8 + 2 * t4;
            float b0 = bias ? __ldg(bias + c) : 0.f;
            float b1 = bias ? __ldg(bias + c + 1) : 0.f;
            float v0 = acc[mt][nt][0] + b0, v1 = acc[mt][nt][1] + b1;
            float v2 = acc[mt][nt][2] + b0, v3 = acc[mt][nt][3] + b1;
            if (relu) {
                v0 = fmaxf(v0, 0.f); v1 = fmaxf(v1, 0.f);
                v2 = fmaxf(v2, 0.f); v3 = fmaxf(v3, 0.f);
            }
            if (Cf) {
                *(float2*)(Cf + (size_t)r0 * N + c) = make_float2(v0, v1);
                *(float2*)(Cf + (size_t)(r0 + 8) * N + c) = make_float2(v2, v3);
            }
            if (Ch) {
                *(__half2*)(Ch + (size_t)r0 * N + c) = __floats2half2_rn(v0, v1);
                *(__half2*)(Ch + (size_t)(r0 + 8) * N + c) = __floats2half2_rn(v2, v3);
            }
        }
    }
}

// ---------------- fp16 tensor-core attention ----------------
// block = (b,h) x 64-row s-tile, 256 threads / 8 warps, 2 CTA/SM.
// smem (halves strides): Q[64][72], KV[128][72], Es[64][520] fp16, ssum[64] fp32
#define SQ_OFF 0
#define SKV_OFF 9216
#define SE_OFF 27648
#define SSUM_OFF 94208
#define ATT_SMEM 94464

__global__ void __launch_bounds__(256, 2) attention_h(
    const __half* __restrict__ qkv, const int* __restrict__ nkeep,
    float* __restrict__ attns, __half* __restrict__ heads) {
    extern __shared__ __align__(128) char smc[];
    uint32_t sbase = smem_u32(smc);
    uint32_t sQ = sbase + SQ_OFF;
    uint32_t sKV = sbase + SKV_OFF;
    uint32_t sE = sbase + SE_OFF;
    float* ssum = (float*)(smc + SSUM_OFF);
    __half* EsH = (__half*)(smc + SE_OFF);

    int bh = blockIdx.x;
    int b = bh >> 3, h = bh & 7;
    int s0 = blockIdx.y * 64;
    int tid = threadIdx.x;
    int wid = tid >> 5, lane = tid & 31;
    int g = lane >> 2, t4 = lane & 3;
    int l15 = lane & 15, l16 = lane >> 4;
    int nk = nkeep[b];
    const float sc = 0.04419417382415922f;  // 1/sqrt(512)
    const int QS = 3 * DM;                  // 1536 halves per row

    if (tid < 64) ssum[tid] = 0.f;

    // async-load Q tile (64 rows x 64 halves)
#pragma unroll
    for (int j = 0; j < 2; j++) {
        int cid = tid + 256 * j;
        int row = cid >> 3, c = cid & 7;
        cpa16(sQ + row * 144 + c * 16,
              qkv + ((size_t)(b * SS + s0 + row)) * QS + h * 64 + c * 8);
    }
    // async-load K chunk 0 (128 rows x 64 halves)
#pragma unroll
    for (int j = 0; j < 4; j++) {
        int cid = tid + 256 * j;
        int row = cid >> 3, c = cid & 7;
        cpa16(sKV + row * 144 + c * 16,
              qkv + ((size_t)(b * SS + row)) * QS + 512 + h * 64 + c * 8);
    }
    asm volatile("cp.async.commit_group;");
    asm volatile("cp.async.wait_group 0;");
    __syncthreads();

    // ---- Phase A: exp(QK^T * sc) -> Es fp16, partial row sums in regs ----
    int wmA = wid >> 2, wnA = wid & 3;  // 2 x 4; warp tile m32 x n32
    float psum[4] = {0.f, 0.f, 0.f, 0.f};

    for (int t0 = 0; t0 < SS; t0 += 128) {
        float acc[2][4][4];
#pragma unroll
        for (int i = 0; i < 2; i++)
#pragma unroll
            for (int j = 0; j < 4; j++)
#pragma unroll
                for (int c = 0; c < 4; c++) acc[i][j][c] = 0.f;

#pragma unroll
        for (int ks = 0; ks < 4; ks++) {
            uint32_t a[2][4];
#pragma unroll
            for (int mt = 0; mt < 2; mt++) {
                int row = wmA * 32 + mt * 16 + l15;
                ldm_x4(a[mt], sQ + row * 144 + ks * 32 + l16 * 16);
            }
            uint32_t bq[2][4];
#pragma unroll
            for (int bt = 0; bt < 2; bt++) {
                int row = wnA * 32 + bt * 16 + l15;
                ldm_x4(bq[bt], sKV + row * 144 + ks * 32 + l16 * 16);
            }
#pragma unroll
            for (int mt = 0; mt < 2; mt++)
#pragma unroll
                for (int nt = 0; nt < 4; nt++)
                    mma_f16(acc[mt][nt], a[mt], bq[nt >> 1][nt & 1], bq[nt >> 1][2 + (nt & 1)]);
        }
        __syncthreads();  // done reading K chunk

        // prefetch next K chunk
        if (t0 + 128 < SS) {
#pragma unroll
            for (int j = 0; j < 4; j++) {
                int cid = tid + 256 * j;
                int row = cid >> 3, c = cid & 7;
                cpa16(sKV + row * 144 + c * 16,
                      qkv + ((size_t)(b * SS + t0 + 128 + row)) * QS + 512 + h * 64 + c * 8);
            }
            asm volatile("cp.async.commit_group;");
        }

        // exp + mask + store fp16 + accumulate partial row sums
#pragma unroll
        for (int mt = 0; mt < 2; mt++) {
            int r0 = wmA * 32 + mt * 16 + g;
#pragma unroll
            for (int nt = 0; nt < 4; nt++) {
                int col = t0 + wnA * 32 + nt * 8 + 2 * t4;
                float e0 = (col     < nk) ? fast_exp(acc[mt][nt][0] * sc) : 0.f;
                float e1 = (col + 1 < nk) ? fast_exp(acc[mt][nt][1] * sc) : 0.f;
                float e2 = (col     < nk) ? fast_exp(acc[mt][nt][2] * sc) : 0.f;
                float e3 = (col + 1 < nk) ? fast_exp(acc[mt][nt][3] * sc) : 0.f;
                *(__half2*)(EsH + r0 * 520 + col) = __floats2half2_rn(e0, e1);
                *(__half2*)(EsH + (r0 + 8) * 520 + col) = __floats2half2_rn(e2, e3);
                psum[mt * 2 + 0] += e0 + e1;
                psum[mt * 2 + 1] += e2 + e3;
            }
        }

        if (t0 + 128 < SS) {
            asm volatile("cp.async.wait_group 0;");
            __syncthreads();
        }
    }

    // merge partial sums
#pragma unroll
    for (int mt = 0; mt < 2; mt++) {
        atomicAdd(&ssum[wmA * 32 + mt * 16 + g], psum[mt * 2 + 0]);
        atomicAdd(&ssum[wmA * 32 + mt * 16 + g + 8], psum[mt * 2 + 1]);
    }
    __syncthreads();
    if (tid < 64) ssum[tid] = 1.f / ssum[tid];
    __syncthreads();

    // attns chunk writer: 64 rows x 128 cols fp32, streaming
    float* attn_base = attns + (((size_t)(h * BB + b)) * SS + s0) * SS;
    auto write_chunk = [&](int t0) {
        for (int i = tid; i < 2048; i += 256) {
            int row = i >> 5, c4 = (i & 31) * 4;
            uint2 u = *(uint2*)(EsH + row * 520 + t0 + c4);
            float2 f0 = __half22float2(*(__half2*)&u.x);
            float2 f1 = __half22float2(*(__half2*)&u.y);
            float riv = ssum[row];
            stcs4(attn_base + (size_t)row * SS + t0 + c4,
                  make_float4(f0.x * riv, f0.y * riv, f1.x * riv, f1.y * riv));
        }
    };

    // prefetch V chunk 0; overlap with attns chunk-0 write
#pragma unroll
    for (int j = 0; j < 4; j++) {
        int cid = tid + 256 * j;
        int row = cid >> 3, c = cid & 7;
        cpa16(sKV + row * 144 + c * 16,
              qkv + ((size_t)(b * SS + row)) * QS + 1024 + h * 64 + c * 8);
    }
    asm volatile("cp.async.commit_group;");
    write_chunk(0);
    asm volatile("cp.async.wait_group 0;");
    __syncthreads();

    // ---- Phase B: O = (Es @ V) * rinv, attns writes interleaved ----
    int wmB = wid >> 1, wnB = wid & 1;  // 4 x 2; warp tile m16 x n32
    float oacc[4][4];
#pragma unroll
    for (int j = 0; j < 4; j++)
#pragma unroll
        for (int c = 0; c < 4; c++) oacc[j][c] = 0.f;

    for (int ci = 0; ci < 4; ci++) {
        int t0 = ci * 128;
#pragma unroll
        for (int k16 = 0; k16 < 8; k16++) {
            uint32_t a[4];
            {
                int row = wmB * 16 + l15;
                ldm_x4(a, sE + row * 1040 + (t0 + k16 * 16) * 2 + l16 * 16);
            }
            uint32_t bt[2][4];
#pragma unroll
            for (int pair = 0; pair < 2; pair++) {
                int kr = k16 * 16 + l15;
                int nv = wnB * 32 + pair * 16 + l16 * 8;
                ldm_x4_t(bt[pair], sKV + kr * 144 + nv * 2);
            }
            // trans-ldmatrix register order: {b0(n-low), b1(n-low), b0(n-high), b1(n-high)}
#pragma unroll
            for (int nt = 0; nt < 4; nt++)
                mma_f16(oacc[nt], a, bt[nt >> 1][(nt & 1) * 2], bt[nt >> 1][(nt & 1) * 2 + 1]);
        }
        __syncthreads();
        if (ci < 3) {
            // prefetch next V chunk, then hide attns store of chunk ci+1 under it
#pragma unroll
            for (int j = 0; j < 4; j++) {
                int cid = tid + 256 * j;
                int row = cid >> 3, c = cid & 7;
                cpa16(sKV + row * 144 + c * 16,
                      qkv + ((size_t)(b * SS + t0 + 128 + row)) * QS + 1024 + h * 64 + c * 8);
            }
            asm volatile("cp.async.commit_group;");
            write_chunk(t0 + 128);
            asm volatile("cp.async.wait_group 0;");
            __syncthreads();
        }
    }

    // write O (fp16 heads)
    {
        int r0 = wmB * 16 + g;
        float ri0 = ssum[r0], ri1 = ssum[r0 + 8];
        size_t base0 = ((size_t)(b * SS + s0 + r0)) * DM + h * 64;
        size_t base1 = ((size_t)(b * SS + s0 + r0 + 8)) * DM + h * 64;
#pragma unroll
        for (int nt = 0; nt < 4; nt++) {
            int c = wnB * 32 + nt * 8 + 2 * t4;
            *(__half2*)(heads + base0 + c) =
                __floats2half2_rn(oacc[nt][0] * ri0, oacc[nt][1] * ri0);
            *(__half2*)(heads + base1 + c) =
                __floats2half2_rn(oacc[nt][2] * ri1, oacc[nt][3] * ri1);
        }
    }
}

// ---------------- layernorm (fp16 in, fp32 math): out_f and/or out_h ----------------
__global__ void ln_kernel(const __half* __restrict__ y, const __half* __restrict__ resid,
                          const float* __restrict__ g, const float* __restrict__ be,
                          float* __restrict__ out_f, __half* __restrict__ out_h) {
    int row = blockIdx.x;
    int tid = threadIdx.x;  // 128
    uint2 uy = ((const uint2*)(y + (size_t)row * DM))[tid];
    uint2 ur = ((const uint2*)(resid + (size_t)row * DM))[tid];
    float2 a0 = __half22float2(*(__half2*)&uy.x);
    float2 a1 = __half22float2(*(__half2*)&uy.y);
    float2 b0 = __half22float2(*(__half2*)&ur.x);
    float2 b1 = __half22float2(*(__half2*)&ur.y);
    float v0 = a0.x + b0.x, v1 = a0.y + b0.y, v2 = a1.x + b1.x, v3 = a1.y + b1.y;
    float s = v0 + v1 + v2 + v3;
    float ss = v0 * v0 + v1 * v1 + v2 * v2 + v3 * v3;
    for (int o = 16; o; o >>= 1) {
        s += __shfl_xor_sync(~0u, s, o);
        ss += __shfl_xor_sync(~0u, ss, o);
    }
    __shared__ float shs[4], shss[4];
    int w = tid >> 5, l = tid & 31;
    if (l == 0) { shs[w] = s; shss[w] = ss; }
    __syncthreads();
    s = shs[0] + shs[1] + shs[2] + shs[3];
    ss = shss[0] + shss[1] + shss[2] + shss[3];
    float mu = s * (1.f / 512.f);
    float var = fmaxf((ss - 512.f * mu * mu) * (1.f / 511.f), 0.f);
    float inv = 1.f / (sqrtf(var) + EPSLN);
    float4 gg = ((const float4*)g)[tid];
    float4 bb = ((const float4*)be)[tid];
    float o0 = (v0 - mu) * inv * gg.x + bb.x;
    float o1 = (v1 - mu) * inv * gg.y + bb.y;
    float o2 = (v2 - mu) * inv * gg.z + bb.z;
    float o3 = (v3 - mu) * inv * gg.w + bb.w;
    if (out_f)
        stcs4(out_f + (size_t)row * DM + tid * 4, make_float4(o0, o1, o2, o3));
    if (out_h) {
        __half2 h0 = __floats2half2_rn(o0, o1);
        __half2 h1 = __floats2half2_rn(o2, o3);
        uint2 u;
        u.x = *(uint32_t*)&h0;
        u.y = *(uint32_t*)&h1;
        ((uint2*)(out_h + (size_t)row * DM))[tid] = u;
    }
}

// ---------------- launch ----------------
extern "C" void kernel_launch(void* const* d_in, const int* in_sizes, int n_in,
                              void* d_out, int out_size) {
    const float* x      = (const float*)d_in[0];
    const float* w_qs   = (const float*)d_in[1];
    const float* w_ks   = (const float*)d_in[2];
    const float* w_vs   = (const float*)d_in[3];
    const float* proj_w = (const float*)d_in[4];
    const float* proj_b = (const float*)d_in[5];
    const float* ln1_g  = (const float*)d_in[6];
    const float* ln1_b  = (const float*)d_in[7];
    const float* ffn_w1 = (const float*)d_in[8];
    const float* ffn_b1 = (const float*)d_in[9];
    const float* ffn_w2 = (const float*)d_in[10];
    const float* ffn_b2 = (const float*)d_in[11];
    const float* ln2_g  = (const float*)d_in[12];
    const float* ln2_b  = (const float*)d_in[13];
    const int*   keepm  = (const int*)d_in[14];

    float* out = (float*)d_out;
    float* enc_out = out;
    float* attns   = out + ENC_ELEMS;

    __half *xch, *qkvh, *headsh, *tmph, *attnouth, *ffnh, *wqkvT, *projwT, *w1T, *w2T;
    int *idx, *nk;
    cudaGetSymbolAddress((void**)&xch, g_xch);
    cudaGetSymbolAddress((void**)&qkvh, g_qkvh);
    cudaGetSymbolAddress((void**)&headsh, g_headsh);
    cudaGetSymbolAddress((void**)&tmph, g_tmph);
    cudaGetSymbolAddress((void**)&attnouth, g_attnouth);
    cudaGetSymbolAddress((void**)&ffnh, g_ffnh);
    cudaGetSymbolAddress((void**)&wqkvT, g_wqkvT);
    cudaGetSymbolAddress((void**)&projwT, g_projwT);
    cudaGetSymbolAddress((void**)&w1T, g_w1T);
    cudaGetSymbolAddress((void**)&w2T, g_w2T);
    cudaGetSymbolAddress((void**)&idx, g_idx);
    cudaGetSymbolAddress((void**)&nk, g_nkeep);

    static int smem_set = 0;
    if (!smem_set) {
        cudaFuncSetAttribute(attention_h, cudaFuncAttributeMaxDynamicSharedMemorySize, ATT_SMEM);
        cudaFuncSetAttribute(hgemm, cudaFuncAttributeMaxDynamicSharedMemorySize, HSM_TOTAL);
        smem_set = 1;
    }

    // 0: all weight prep (3 transposes + qkv pack) in one launch
    prep_all<<<dim3(64, 64, 4), dim3(32, 8)>>>(proj_w, ffn_w1, ffn_w2, w_qs, w_ks, w_vs,
                                               projwT, w1T, w2T, wqkvT);
    // 1: skipper
    skipper_scan<<<BB, SS>>>(keepm, idx, nk);
    // 2: gather (fp16 only)
    gather_kernel<<<MTOT / 2, 256>>>(x, idx, nk, xch);
    // 3: fused QKV projection -> fp16 qkv
    hgemm<<<dim3(1536 / 256, MTOT / 128), 256, HSM_TOTAL>>>(
        xch, wqkvT, nullptr, qkvh, MTOT, 1536, DM, nullptr, 0);
    // 4: fp16 attention (writes attns fp32 + heads fp16)
    attention_h<<<dim3(BB * NH, SS / 64), 256, ATT_SMEM>>>(qkvh, nk, attns, headsh);
    // 5: output projection (fp16 out)
    hgemm<<<dim3(DM / 256, MTOT / 128), 256, HSM_TOTAL>>>(
        headsh, projwT, nullptr, tmph, MTOT, DM, DM, proj_b, 0);
    // 6: LN1 (fp16 out only)
    ln_kernel<<<MTOT, 128>>>(tmph, xch, ln1_g, ln1_b, nullptr, attnouth);
    // 7: FFN1 (relu, fp16 out)
    hgemm<<<dim3(DINNER / 256, MTOT / 128), 256, HSM_TOTAL>>>(
        attnouth, w1T, nullptr, ffnh, MTOT, DINNER, DM, ffn_b1, 1);
    // 8: FFN2 (fp16 out)
    hgemm<<<dim3(DM / 256, MTOT / 128), 256, HSM_TOTAL>>>(
        ffnh, w2T, nullptr, tmph, MTOT, DM, DINNER, ffn_b2, 0);
    // 9: LN2 -> enc_out fp32
    ln_kernel<<<MTOT, 128>>>(tmph, attnouth, ln2_g, ln2_b, enc_out, nullptr);
}

// round 14
// speedup vs baseline: 1.1115x; 1.1115x over previous
#include <cuda_runtime.h>
#include <cuda_fp16.h>
#include <math.h>
#include <stdint.h>

// ---------------- problem constants ----------------
#define BB 32
#define SS 512
#define DM 512
#define NH 8
#define DK 64
#define DINNER 2048
#define MTOT (BB * SS)              // 16384 rows
#define ENC_ELEMS (BB * SS * DM)    // 8388608
#define EPSLN 1e-3f

// ---------------- scratch (device globals; no allocation allowed) ----------------
__device__ __half g_xch[MTOT * DM];         // compacted input fp16 (GEMM A + LN1 residual)
__device__ __half g_qkvh[MTOT * 3 * DM];    // merged q|k|v  [row][1536] fp16
__device__ __half g_headsh[MTOT * DM];      // attn heads (fp16)
__device__ __half g_tmph[MTOT * DM];        // pre-LN gemm out (fp16, reused)
__device__ __half g_attnouth[MTOT * DM];    // LN1 output (fp16)
__device__ __half g_ffnh[MTOT * DINNER];    // FFN hidden (fp16, relu'd)
__device__ __half g_wqkvT[1536 * DM];       // [n][k] fp16
__device__ __half g_projwT[DM * DM];
__device__ __half g_w1T[DINNER * DM];
__device__ __half g_w2T[DM * DINNER];
__device__ int    g_idx[BB * SS];
__device__ int    g_nkeep[BB];

// ---------------- helpers ----------------
__device__ __forceinline__ void cpa16(uint32_t dst, const void* src) {
    asm volatile("cp.async.cg.shared.global [%0], [%1], 16;" :: "r"(dst), "l"(src));
}
__device__ __forceinline__ void ldm_x4(uint32_t* r, uint32_t addr) {
    asm volatile("ldmatrix.sync.aligned.m8n8.x4.shared.b16 {%0,%1,%2,%3}, [%4];"
                 : "=r"(r[0]), "=r"(r[1]), "=r"(r[2]), "=r"(r[3]) : "r"(addr));
}
__device__ __forceinline__ void ldm_x4_t(uint32_t* r, uint32_t addr) {
    asm volatile("ldmatrix.sync.aligned.m8n8.x4.trans.shared.b16 {%0,%1,%2,%3}, [%4];"
                 : "=r"(r[0]), "=r"(r[1]), "=r"(r[2]), "=r"(r[3]) : "r"(addr));
}
__device__ __forceinline__ void mma_f16(float* d, const uint32_t* a, uint32_t b0, uint32_t b1) {
    asm volatile(
        "mma.sync.aligned.m16n8k16.row.col.f32.f16.f16.f32 "
        "{%0,%1,%2,%3}, {%4,%5,%6,%7}, {%8,%9}, {%0,%1,%2,%3};"
        : "+f"(d[0]), "+f"(d[1]), "+f"(d[2]), "+f"(d[3])
        : "r"(a[0]), "r"(a[1]), "r"(a[2]), "r"(a[3]), "r"(b0), "r"(b1));
}
__device__ __forceinline__ float fast_exp(float x) {
    float t = x * 1.4426950408889634f;
    float z = t + 12582912.0f;
    int   m = __float_as_int(z) - 0x4B400000;
    float f = t - (z - 12582912.0f);
    float p = 1.3333558146e-3f;
    p = fmaf(p, f, 9.6181291076e-3f);
    p = fmaf(p, f, 5.5504108665e-2f);
    p = fmaf(p, f, 2.4022650696e-1f);
    p = fmaf(p, f, 6.9314718056e-1f);
    p = fmaf(p, f, 1.0f);
    return __int_as_float(__float_as_int(p) + (m << 23));
}
__device__ __forceinline__ uint32_t smem_u32(const void* p) {
    uint32_t a;
    asm("{ .reg .u64 t; cvta.to.shared.u64 t, %1; cvt.u32.u64 %0, t; }" : "=r"(a) : "l"(p));
    return a;
}
__device__ __forceinline__ void stcs4(float* p, float4 v) {
    asm volatile("st.global.cs.v4.f32 [%0], {%1,%2,%3,%4};"
                 :: "l"(p), "f"(v.x), "f"(v.y), "f"(v.z), "f"(v.w) : "memory");
}

// ---------------- weight prep: 3 transposes + qkv pack in ONE launch ----------------
__global__ void prep_all(const float* __restrict__ proj_w, const float* __restrict__ w1,
                         const float* __restrict__ w2, const float* __restrict__ wq,
                         const float* __restrict__ wk, const float* __restrict__ wv,
                         __half* __restrict__ projwT, __half* __restrict__ w1T,
                         __half* __restrict__ w2T, __half* __restrict__ wqkvT) {
    int z = blockIdx.z;
    int tx = threadIdx.x, ty = threadIdx.y;  // 32 x 8
    if (z == 3) {
        int lb = blockIdx.y * 64 + blockIdx.x;
        if (lb >= 3072) return;
        int i = lb * 256 + ty * 32 + tx;
        int n = i >> 9;
        int d = i & 511;
        int sel = n >> 9;
        int nn = n & 511;
        int h = nn >> 6, kk = nn & 63;
        const float* w = (sel == 0) ? wq : (sel == 1) ? wk : wv;
        wqkvT[i] = __float2half_rn(w[(h * DM + d) * DK + kk]);
        return;
    }
    __shared__ float t[32][33];
    const float* in;
    __half* out;
    int R, C;
    if (z == 0)      { in = proj_w; out = projwT; R = DM;     C = DM; }
    else if (z == 1) { in = w1;     out = w1T;    R = DM;     C = DINNER; }
    else             { in = w2;     out = w2T;    R = DINNER; C = DM; }
    int c0 = blockIdx.x * 32, r0 = blockIdx.y * 32;
    if (c0 >= C || r0 >= R) return;
#pragma unroll
    for (int j = 0; j < 32; j += 8)
        t[ty + j][tx] = in[(size_t)(r0 + ty + j) * C + c0 + tx];
    __syncthreads();
#pragma unroll
    for (int j = 0; j < 32; j += 8)
        out[(size_t)(c0 + ty + j) * R + r0 + tx] = __float2half_rn(t[tx][ty + j]);
}

// ---------------- skipper ----------------
__global__ void skipper_scan(const int* __restrict__ keep, int* __restrict__ idx,
                             int* __restrict__ nkeep) {
    int b = blockIdx.x, t = threadIdx.x;
    __shared__ int sh[SS];
    int v = keep[b * SS + t] > 0;
    sh[t] = v;
    __syncthreads();
    for (int off = 1; off < SS; off <<= 1) {
        int x = (t >= off) ? sh[t - off] : 0;
        __syncthreads();
        sh[t] += x;
        __syncthreads();
    }
    int incl = sh[t];
    if (v) idx[b * SS + incl - 1] = t;
    if (t == SS - 1) nkeep[b] = incl;
}

// 2 rows per 256-thread block
__global__ void gather_kernel(const float* __restrict__ x, const int* __restrict__ idx,
                              const int* __restrict__ nkeep, __half* __restrict__ xch) {
    int bs = blockIdx.x * 2 + (threadIdx.x >> 7);
    int t = threadIdx.x & 127;
    int b = bs >> 9, s = bs & 511;
    int nk = nkeep[b];
    float4 v = make_float4(0.f, 0.f, 0.f, 0.f);
    if (s < nk)
        v = ((const float4*)(x + ((size_t)b * SS + idx[b * SS + s]) * DM))[t];
    __half2 h0 = __floats2half2_rn(v.x, v.y);
    __half2 h1 = __floats2half2_rn(v.z, v.w);
    uint2 u;
    u.x = *(uint32_t*)&h0;
    u.y = *(uint32_t*)&h1;
    ((uint2*)(xch + (size_t)bs * DM))[t] = u;
}

// ---------------- fp16 tensor-core GEMM (128x128 tile, BK=64, 3-stage) ----------------
// exact R9 structure (best measured config)
#define HSM_TOTAL 98304   // 3 x (16K A + 16K B)

__global__ void __launch_bounds__(256, 2) hgemm(
    const __half* __restrict__ A, const __half* __restrict__ Bt,
    float* __restrict__ Cf, __half* __restrict__ Ch,
    int M, int N, int K, const float* __restrict__ bias, int relu) {
    extern __shared__ __align__(128) char smc[];
    uint32_t sbase = smem_u32(smc);     // A bufs: 0..49152, B bufs: 49152..98304

    int tid = threadIdx.x;
    int wid = tid >> 5, lane = tid & 31;
    int g = lane >> 2, t4 = lane & 3;
    int l15 = lane & 15, l16 = lane >> 4;
    int wm = wid >> 2, wn = wid & 3;
    int rowBase = blockIdx.y * 128;
    int colBase = blockIdx.x * 128;

    float acc[4][4][4];
#pragma unroll
    for (int i = 0; i < 4; i++)
#pragma unroll
        for (int j = 0; j < 4; j++)
#pragma unroll
            for (int c = 0; c < 4; c++) acc[i][j][c] = 0.f;

    const int nc = K / 64;

    auto load_tile = [&](int kt, int buf) {
        int k0 = kt * 64;
#pragma unroll
        for (int j = 0; j < 4; j++) {
            int cid = tid + 256 * j;
            int row = cid >> 3, c = cid & 7;
            uint32_t off = row * 128 + ((c ^ (row & 7)) << 4);
            cpa16(sbase + buf * 16384 + off,
                  A + (size_t)(rowBase + row) * K + k0 + c * 8);
            cpa16(sbase + 49152 + buf * 16384 + off,
                  Bt + (size_t)(colBase + row) * K + k0 + c * 8);
        }
        asm volatile("cp.async.commit_group;");
    };

    load_tile(0, 0);
    if (nc > 1) load_tile(1, 1);

    for (int kt = 0; kt < nc; kt++) {
        int buf = kt % 3;
        if (kt + 2 < nc) {
            load_tile(kt + 2, (kt + 2) % 3);
            asm volatile("cp.async.wait_group 2;");
        } else if (kt + 1 < nc) {
            asm volatile("cp.async.wait_group 1;");
        } else {
            asm volatile("cp.async.wait_group 0;");
        }
        __syncthreads();

        uint32_t aBase = sbase + buf * 16384;
        uint32_t bBase = sbase + 49152 + buf * 16384;
#pragma unroll
        for (int ks = 0; ks < 4; ks++) {
            int ch = 2 * ks + l16;
            uint32_t a[4][4];
#pragma unroll
            for (int mt = 0; mt < 4; mt++) {
                int row = wm * 64 + mt * 16 + l15;
                ldm_x4(a[mt], aBase + row * 128 + ((ch ^ (row & 7)) << 4));
            }
            uint32_t bq[2][4];
#pragma unroll
            for (int bt = 0; bt < 2; bt++) {
                int row = wn * 32 + bt * 16 + l15;
                ldm_x4(bq[bt], bBase + row * 128 + ((ch ^ (row & 7)) << 4));
            }
#pragma unroll
            for (int mt = 0; mt < 4; mt++)
#pragma unroll
                for (int nt = 0; nt < 4; nt++)
                    mma_f16(acc[mt][nt], a[mt], bq[nt >> 1][nt & 1], bq[nt >> 1][2 + (nt & 1)]);
        }
        __syncthreads();
    }

#pragma unroll
    for (int mt = 0; mt < 4; mt++) {
        int r0 = rowBase + wm * 64 + mt * 16 + g;
#pragma unroll
        for (int nt = 0; nt < 4; nt++) {
            int c = colBase + wn * 32 + nt * 8 + 2 * t4;
            float b0 = bias ? __ldg(bias + c) : 0.f;
            float b1 = bias ? __ldg(bias + c + 1) : 0.f;
            float v0 = acc[mt][nt][0] + b0, v1 = acc[mt][nt][1] + b1;
            float v2 = acc[mt][nt][2] + b0, v3 = acc[mt][nt][3] + b1;
            if (relu) {
                v0 = fmaxf(v0, 0.f); v1 = fmaxf(v1, 0.f);
                v2 = fmaxf(v2, 0.f); v3 = fmaxf(v3, 0.f);
            }
            if (Cf) {
                *(float2*)(Cf + (size_t)r0 * N + c) = make_float2(v0, v1);
                *(float2*)(Cf + (size_t)(r0 + 8) * N + c) = make_float2(v2, v3);
            }
            if (Ch) {
                *(__half2*)(Ch + (size_t)r0 * N + c) = __floats2half2_rn(v0, v1);
                *(__half2*)(Ch + (size_t)(r0 + 8) * N + c) = __floats2half2_rn(v2, v3);
            }
        }
    }
}

// ---------------- fp16 tensor-core attention (masked-chunk skipping) ----------------
// block = (b,h) x 64-row s-tile, 256 threads / 8 warps, 2 CTA/SM.
// smem (halves strides): Q[64][72], KV[128][72], Es[64][520] fp16, ssum[64] fp32
#define SQ_OFF 0
#define SKV_OFF 9216
#define SE_OFF 27648
#define SSUM_OFF 94208
#define ATT_SMEM 94464

__global__ void __launch_bounds__(256, 2) attention_h(
    const __half* __restrict__ qkv, const int* __restrict__ nkeep,
    float* __restrict__ attns, __half* __restrict__ heads) {
    extern __shared__ __align__(128) char smc[];
    uint32_t sbase = smem_u32(smc);
    uint32_t sQ = sbase + SQ_OFF;
    uint32_t sKV = sbase + SKV_OFF;
    uint32_t sE = sbase + SE_OFF;
    float* ssum = (float*)(smc + SSUM_OFF);
    __half* EsH = (__half*)(smc + SE_OFF);

    int bh = blockIdx.x;
    int b = bh >> 3, h = bh & 7;
    int s0 = blockIdx.y * 64;
    int tid = threadIdx.x;
    int wid = tid >> 5, lane = tid & 31;
    int g = lane >> 2, t4 = lane & 3;
    int l15 = lane & 15, l16 = lane >> 4;
    int nk = nkeep[b];
    int kc = (nk + 127) >> 7;               // chunks of keys to actually compute
    if (kc < 1) kc = 1;
    if (kc > 4) kc = 4;
    const float sc = 0.04419417382415922f;  // 1/sqrt(512)
    const int QS = 3 * DM;                  // 1536 halves per row

    if (tid < 64) ssum[tid] = 0.f;

    // async-load Q tile (64 rows x 64 halves)
#pragma unroll
    for (int j = 0; j < 2; j++) {
        int cid = tid + 256 * j;
        int row = cid >> 3, c = cid & 7;
        cpa16(sQ + row * 144 + c * 16,
              qkv + ((size_t)(b * SS + s0 + row)) * QS + h * 64 + c * 8);
    }
    // async-load K chunk 0 (128 rows x 64 halves)
#pragma unroll
    for (int j = 0; j < 4; j++) {
        int cid = tid + 256 * j;
        int row = cid >> 3, c = cid & 7;
        cpa16(sKV + row * 144 + c * 16,
              qkv + ((size_t)(b * SS + row)) * QS + 512 + h * 64 + c * 8);
    }
    asm volatile("cp.async.commit_group;");
    asm volatile("cp.async.wait_group 0;");
    __syncthreads();

    // ---- Phase A: exp(QK^T * sc) -> Es fp16 for kc chunks only ----
    int wmA = wid >> 2, wnA = wid & 3;  // 2 x 4; warp tile m32 x n32
    float psum[4] = {0.f, 0.f, 0.f, 0.f};
    int lim = kc * 128;

    for (int t0 = 0; t0 < lim; t0 += 128) {
        float acc[2][4][4];
#pragma unroll
        for (int i = 0; i < 2; i++)
#pragma unroll
            for (int j = 0; j < 4; j++)
#pragma unroll
                for (int c = 0; c < 4; c++) acc[i][j][c] = 0.f;

#pragma unroll
        for (int ks = 0; ks < 4; ks++) {
            uint32_t a[2][4];
#pragma unroll
            for (int mt = 0; mt < 2; mt++) {
                int row = wmA * 32 + mt * 16 + l15;
                ldm_x4(a[mt], sQ + row * 144 + ks * 32 + l16 * 16);
            }
            uint32_t bq[2][4];
#pragma unroll
            for (int bt = 0; bt < 2; bt++) {
                int row = wnA * 32 + bt * 16 + l15;
                ldm_x4(bq[bt], sKV + row * 144 + ks * 32 + l16 * 16);
            }
#pragma unroll
            for (int mt = 0; mt < 2; mt++)
#pragma unroll
                for (int nt = 0; nt < 4; nt++)
                    mma_f16(acc[mt][nt], a[mt], bq[nt >> 1][nt & 1], bq[nt >> 1][2 + (nt & 1)]);
        }
        __syncthreads();  // done reading K chunk

        // prefetch next K chunk
        if (t0 + 128 < lim) {
#pragma unroll
            for (int j = 0; j < 4; j++) {
                int cid = tid + 256 * j;
                int row = cid >> 3, c = cid & 7;
                cpa16(sKV + row * 144 + c * 16,
                      qkv + ((size_t)(b * SS + t0 + 128 + row)) * QS + 512 + h * 64 + c * 8);
            }
            asm volatile("cp.async.commit_group;");
        }

        // exp + mask + store fp16 + accumulate partial row sums
#pragma unroll
        for (int mt = 0; mt < 2; mt++) {
            int r0 = wmA * 32 + mt * 16 + g;
#pragma unroll
            for (int nt = 0; nt < 4; nt++) {
                int col = t0 + wnA * 32 + nt * 8 + 2 * t4;
                float e0 = (col     < nk) ? fast_exp(acc[mt][nt][0] * sc) : 0.f;
                float e1 = (col + 1 < nk) ? fast_exp(acc[mt][nt][1] * sc) : 0.f;
                float e2 = (col     < nk) ? fast_exp(acc[mt][nt][2] * sc) : 0.f;
                float e3 = (col + 1 < nk) ? fast_exp(acc[mt][nt][3] * sc) : 0.f;
                *(__half2*)(EsH + r0 * 520 + col) = __floats2half2_rn(e0, e1);
                *(__half2*)(EsH + (r0 + 8) * 520 + col) = __floats2half2_rn(e2, e3);
                psum[mt * 2 + 0] += e0 + e1;
                psum[mt * 2 + 1] += e2 + e3;
            }
        }

        if (t0 + 128 < lim) {
            asm volatile("cp.async.wait_group 0;");
            __syncthreads();
        }
    }

    // merge partial sums
#pragma unroll
    for (int mt = 0; mt < 2; mt++) {
        atomicAdd(&ssum[wmA * 32 + mt * 16 + g], psum[mt * 2 + 0]);
        atomicAdd(&ssum[wmA * 32 + mt * 16 + g + 8], psum[mt * 2 + 1]);
    }
    __syncthreads();
    if (tid < 64) ssum[tid] = 1.f / ssum[tid];
    __syncthreads();

    float* attn_base = attns + (((size_t)(h * BB + b)) * SS + s0) * SS;
    // normalized-P chunk writer (reads Es)
    auto write_chunk = [&](int t0) {
        for (int i = tid; i < 2048; i += 256) {
            int row = i >> 5, c4 = (i & 31) * 4;
            uint2 u = *(uint2*)(EsH + row * 520 + t0 + c4);
            float2 f0 = __half22float2(*(__half2*)&u.x);
            float2 f1 = __half22float2(*(__half2*)&u.y);
            float riv = ssum[row];
            stcs4(attn_base + (size_t)row * SS + t0 + c4,
                  make_float4(f0.x * riv, f0.y * riv, f1.x * riv, f1.y * riv));
        }
    };

    // fully-masked chunks: write zeros directly (no Es)
    for (int ci = kc; ci < 4; ci++) {
        int t0 = ci * 128;
        for (int i = tid; i < 2048; i += 256) {
            int row = i >> 5, c4 = (i & 31) * 4;
            stcs4(attn_base + (size_t)row * SS + t0 + c4, make_float4(0.f, 0.f, 0.f, 0.f));
        }
    }

    // prefetch V chunk 0; overlap with attns chunk-0 write
#pragma unroll
    for (int j = 0; j < 4; j++) {
        int cid = tid + 256 * j;
        int row = cid >> 3, c = cid & 7;
        cpa16(sKV + row * 144 + c * 16,
              qkv + ((size_t)(b * SS + row)) * QS + 1024 + h * 64 + c * 8);
    }
    asm volatile("cp.async.commit_group;");
    write_chunk(0);
    asm volatile("cp.async.wait_group 0;");
    __syncthreads();

    // ---- Phase B: O = (Es @ V) * rinv over kc chunks, attns writes interleaved ----
    int wmB = wid >> 1, wnB = wid & 1;  // 4 x 2; warp tile m16 x n32
    float oacc[4][4];
#pragma unroll
    for (int j = 0; j < 4; j++)
#pragma unroll
        for (int c = 0; c < 4; c++) oacc[j][c] = 0.f;

    for (int ci = 0; ci < kc; ci++) {
        int t0 = ci * 128;
#pragma unroll
        for (int k16 = 0; k16 < 8; k16++) {
            uint32_t a[4];
            {
                int row = wmB * 16 + l15;
                ldm_x4(a, sE + row * 1040 + (t0 + k16 * 16) * 2 + l16 * 16);
            }
            uint32_t bt[2][4];
#pragma unroll
            for (int pair = 0; pair < 2; pair++) {
                int kr = k16 * 16 + l15;
                int nv = wnB * 32 + pair * 16 + l16 * 8;
                ldm_x4_t(bt[pair], sKV + kr * 144 + nv * 2);
            }
            // trans-ldmatrix register order: {b0(n-low), b1(n-low), b0(n-high), b1(n-high)}
#pragma unroll
            for (int nt = 0; nt < 4; nt++)
                mma_f16(oacc[nt], a, bt[nt >> 1][(nt & 1) * 2], bt[nt >> 1][(nt & 1) * 2 + 1]);
        }
        __syncthreads();
        if (ci + 1 < kc) {
            // prefetch next V chunk, then hide attns store of chunk ci+1 under it
#pragma unroll
            for (int j = 0; j < 4; j++) {
                int cid = tid + 256 * j;
                int row = cid >> 3, c = cid & 7;
                cpa16(sKV + row * 144 + c * 16,
                      qkv + ((size_t)(b * SS + t0 + 128 + row)) * QS + 1024 + h * 64 + c * 8);
            }
            asm volatile("cp.async.commit_group;");
            write_chunk(t0 + 128);
            asm volatile("cp.async.wait_group 0;");
            __syncthreads();
        }
    }

    // write O (fp16 heads)
    {
        int r0 = wmB * 16 + g;
        float ri0 = ssum[r0], ri1 = ssum[r0 + 8];
        size_t base0 = ((size_t)(b * SS + s0 + r0)) * DM + h * 64;
        size_t base1 = ((size_t)(b * SS + s0 + r0 + 8)) * DM + h * 64;
#pragma unroll
        for (int nt = 0; nt < 4; nt++) {
            int c = wnB * 32 + nt * 8 + 2 * t4;
            *(__half2*)(heads + base0 + c) =
                __floats2half2_rn(oacc[nt][0] * ri0, oacc[nt][1] * ri0);
            *(__half2*)(heads + base1 + c) =
                __floats2half2_rn(oacc[nt][2] * ri1, oacc[nt][3] * ri1);
        }
    }
}

// ---------------- layernorm (fp16 in, fp32 math): out_f and/or out_h ----------------
__global__ void ln_kernel(const __half* __restrict__ y, const __half* __restrict__ resid,
                          const float* __restrict__ g, const float* __restrict__ be,
                          float* __restrict__ out_f, __half* __restrict__ out_h) {
    int row = blockIdx.x;
    int tid = threadIdx.x;  // 128
    uint2 uy = ((const uint2*)(y + (size_t)row * DM))[tid];
    uint2 ur = ((const uint2*)(resid + (size_t)row * DM))[tid];
    float2 a0 = __half22float2(*(__half2*)&uy.x);
    float2 a1 = __half22float2(*(__half2*)&uy.y);
    float2 b0 = __half22float2(*(__half2*)&ur.x);
    float2 b1 = __half22float2(*(__half2*)&ur.y);
    float v0 = a0.x + b0.x, v1 = a0.y + b0.y, v2 = a1.x + b1.x, v3 = a1.y + b1.y;
    float s = v0 + v1 + v2 + v3;
    float ss = v0 * v0 + v1 * v1 + v2 * v2 + v3 * v3;
    for (int o = 16; o; o >>= 1) {
        s += __shfl_xor_sync(~0u, s, o);
        ss += __shfl_xor_sync(~0u, ss, o);
    }
    __shared__ float shs[4], shss[4];
    int w = tid >> 5, l = tid & 31;
    if (l == 0) { shs[w] = s; shss[w] = ss; }
    __syncthreads();
    s = shs[0] + shs[1] + shs[2] + shs[3];
    ss = shss[0] + shss[1] + shss[2] + shss[3];
    float mu = s * (1.f / 512.f);
    float var = fmaxf((ss - 512.f * mu * mu) * (1.f / 511.f), 0.f);
    float inv = 1.f / (sqrtf(var) + EPSLN);
    float4 gg = ((const float4*)g)[tid];
    float4 bb = ((const float4*)be)[tid];
    float o0 = (v0 - mu) * inv * gg.x + bb.x;
    float o1 = (v1 - mu) * inv * gg.y + bb.y;
    float o2 = (v2 - mu) * inv * gg.z + bb.z;
    float o3 = (v3 - mu) * inv * gg.w + bb.w;
    if (out_f)
        stcs4(out_f + (size_t)row * DM + tid * 4, make_float4(o0, o1, o2, o3));
    if (out_h) {
        __half2 h0 = __floats2half2_rn(o0, o1);
        __half2 h1 = __floats2half2_rn(o2, o3);
        uint2 u;
        u.x = *(uint32_t*)&h0;
        u.y = *(uint32_t*)&h1;
        ((uint2*)(out_h + (size_t)row * DM))[tid] = u;
    }
}

// ---------------- launch ----------------
extern "C" void kernel_launch(void* const* d_in, const int* in_sizes, int n_in,
                              void* d_out, int out_size) {
    const float* x      = (const float*)d_in[0];
    const float* w_qs   = (const float*)d_in[1];
    const float* w_ks   = (const float*)d_in[2];
    const float* w_vs   = (const float*)d_in[3];
    const float* proj_w = (const float*)d_in[4];
    const float* proj_b = (const float*)d_in[5];
    const float* ln1_g  = (const float*)d_in[6];
    const float* ln1_b  = (const float*)d_in[7];
    const float* ffn_w1 = (const float*)d_in[8];
    const float* ffn_b1 = (const float*)d_in[9];
    const float* ffn_w2 = (const float*)d_in[10];
    const float* ffn_b2 = (const float*)d_in[11];
    const float* ln2_g  = (const float*)d_in[12];
    const float* ln2_b  = (const float*)d_in[13];
    const int*   keepm  = (const int*)d_in[14];

    float* out = (float*)d_out;
    float* enc_out = out;
    float* attns   = out + ENC_ELEMS;

    __half *xch, *qkvh, *headsh, *tmph, *attnouth, *ffnh, *wqkvT, *projwT, *w1T, *w2T;
    int *idx, *nk;
    cudaGetSymbolAddress((void**)&xch, g_xch);
    cudaGetSymbolAddress((void**)&qkvh, g_qkvh);
    cudaGetSymbolAddress((void**)&headsh, g_headsh);
    cudaGetSymbolAddress((void**)&tmph, g_tmph);
    cudaGetSymbolAddress((void**)&attnouth, g_attnouth);
    cudaGetSymbolAddress((void**)&ffnh, g_ffnh);
    cudaGetSymbolAddress((void**)&wqkvT, g_wqkvT);
    cudaGetSymbolAddress((void**)&projwT, g_projwT);
    cudaGetSymbolAddress((void**)&w1T, g_w1T);
    cudaGetSymbolAddress((void**)&w2T, g_w2T);
    cudaGetSymbolAddress((void**)&idx, g_idx);
    cudaGetSymbolAddress((void**)&nk, g_nkeep);

    static int smem_set = 0;
    if (!smem_set) {
        cudaFuncSetAttribute(attention_h, cudaFuncAttributeMaxDynamicSharedMemorySize, ATT_SMEM);
        cudaFuncSetAttribute(hgemm, cudaFuncAttributeMaxDynamicSharedMemorySize, HSM_TOTAL);
        smem_set = 1;
    }

    // 0: all weight prep (3 transposes + qkv pack) in one launch
    prep_all<<<dim3(64, 64, 4), dim3(32, 8)>>>(proj_w, ffn_w1, ffn_w2, w_qs, w_ks, w_vs,
                                               projwT, w1T, w2T, wqkvT);
    // 1: skipper
    skipper_scan<<<BB, SS>>>(keepm, idx, nk);
    // 2: gather (fp16 only)
    gather_kernel<<<MTOT / 2, 256>>>(x, idx, nk, xch);
    // 3: fused QKV projection -> fp16 qkv
    hgemm<<<dim3(1536 / 128, MTOT / 128), 256, HSM_TOTAL>>>(
        xch, wqkvT, nullptr, qkvh, MTOT, 1536, DM, nullptr, 0);
    // 4: fp16 attention (writes attns fp32 + heads fp16)
    attention_h<<<dim3(BB * NH, SS / 64), 256, ATT_SMEM>>>(qkvh, nk, attns, headsh);
    // 5: output projection (fp16 out)
    hgemm<<<dim3(DM / 128, MTOT / 128), 256, HSM_TOTAL>>>(
        headsh, projwT, nullptr, tmph, MTOT, DM, DM, proj_b, 0);
    // 6: LN1 (fp16 out only)
    ln_kernel<<<MTOT, 128>>>(tmph, xch, ln1_g, ln1_b, nullptr, attnouth);
    // 7: FFN1 (relu, fp16 out)
    hgemm<<<dim3(DINNER / 128, MTOT / 128), 256, HSM_TOTAL>>>(
        attnouth, w1T, nullptr, ffnh, MTOT, DINNER, DM, ffn_b1, 1);
    // 8: FFN2 (fp16 out)
    hgemm<<<dim3(DM / 128, MTOT / 128), 256, HSM_TOTAL>>>(
        ffnh, w2T, nullptr, tmph, MTOT, DM, DINNER, ffn_b2, 0);
    // 9: LN2 -> enc_out fp32
    ln_kernel<<<MTOT, 128>>>(tmph, attnouth, ln2_g, ln2_b, enc_out, nullptr);
}

// round 16
// speedup vs baseline: 1.1860x; 1.0670x over previous
#include <cuda_runtime.h>
#include <cuda_fp16.h>
#include <math.h>
#include <stdint.h>

// ---------------- problem constants ----------------
#define BB 32
#define SS 512
#define DM 512
#define NH 8
#define DK 64
#define DINNER 2048
#define MTOT (BB * SS)              // 16384 rows
#define ENC_ELEMS (BB * SS * DM)    // 8388608
#define EPSLN 1e-3f

// ---------------- scratch (device globals; no allocation allowed) ----------------
__device__ __half g_xch[MTOT * DM];         // compacted input fp16 (GEMM A + LN1 residual)
__device__ __half g_qkvh[MTOT * 3 * DM];    // merged q|k|v  [row][1536] fp16
__device__ __half g_headsh[MTOT * DM];      // attn heads (fp16)
__device__ __half g_tmph[MTOT * DM];        // pre-LN gemm out (fp16, reused)
__device__ __half g_attnouth[MTOT * DM];    // LN1 output (fp16)
__device__ __half g_ffnh[MTOT * DINNER];    // FFN hidden (fp16, relu'd)
__device__ __half g_wqkvT[1536 * DM];       // [n][k] fp16
__device__ __half g_projwT[DM * DM];
__device__ __half g_w1T[DINNER * DM];
__device__ __half g_w2T[DM * DINNER];
__device__ int    g_idx[BB * SS];
__device__ int    g_nkeep[BB];

// ---------------- helpers ----------------
__device__ __forceinline__ void cpa16(uint32_t dst, const void* src) {
    asm volatile("cp.async.cg.shared.global [%0], [%1], 16;" :: "r"(dst), "l"(src));
}
__device__ __forceinline__ void ldm_x4(uint32_t* r, uint32_t addr) {
    asm volatile("ldmatrix.sync.aligned.m8n8.x4.shared.b16 {%0,%1,%2,%3}, [%4];"
                 : "=r"(r[0]), "=r"(r[1]), "=r"(r[2]), "=r"(r[3]) : "r"(addr));
}
__device__ __forceinline__ void ldm_x4_t(uint32_t* r, uint32_t addr) {
    asm volatile("ldmatrix.sync.aligned.m8n8.x4.trans.shared.b16 {%0,%1,%2,%3}, [%4];"
                 : "=r"(r[0]), "=r"(r[1]), "=r"(r[2]), "=r"(r[3]) : "r"(addr));
}
__device__ __forceinline__ void mma_f16(float* d, const uint32_t* a, uint32_t b0, uint32_t b1) {
    asm volatile(
        "mma.sync.aligned.m16n8k16.row.col.f32.f16.f16.f32 "
        "{%0,%1,%2,%3}, {%4,%5,%6,%7}, {%8,%9}, {%0,%1,%2,%3};"
        : "+f"(d[0]), "+f"(d[1]), "+f"(d[2]), "+f"(d[3])
        : "r"(a[0]), "r"(a[1]), "r"(a[2]), "r"(a[3]), "r"(b0), "r"(b1));
}
__device__ __forceinline__ float fast_exp(float x) {
    float t = x * 1.4426950408889634f;
    float z = t + 12582912.0f;
    int   m = __float_as_int(z) - 0x4B400000;
    float f = t - (z - 12582912.0f);
    float p = 1.3333558146e-3f;
    p = fmaf(p, f, 9.6181291076e-3f);
    p = fmaf(p, f, 5.5504108665e-2f);
    p = fmaf(p, f, 2.4022650696e-1f);
    p = fmaf(p, f, 6.9314718056e-1f);
    p = fmaf(p, f, 1.0f);
    return __int_as_float(__float_as_int(p) + (m << 23));
}
__device__ __forceinline__ uint32_t smem_u32(const void* p) {
    uint32_t a;
    asm("{ .reg .u64 t; cvta.to.shared.u64 t, %1; cvt.u32.u64 %0, t; }" : "=r"(a) : "l"(p));
    return a;
}
__device__ __forceinline__ void stcs4(float* p, float4 v) {
    asm volatile("st.global.cs.v4.f32 [%0], {%1,%2,%3,%4};"
                 :: "l"(p), "f"(v.x), "f"(v.y), "f"(v.z), "f"(v.w) : "memory");
}

// ---------------- weight prep: 3 transposes + qkv pack in ONE launch ----------------
__global__ void prep_all(const float* __restrict__ proj_w, const float* __restrict__ w1,
                         const float* __restrict__ w2, const float* __restrict__ wq,
                         const float* __restrict__ wk, const float* __restrict__ wv,
                         __half* __restrict__ projwT, __half* __restrict__ w1T,
                         __half* __restrict__ w2T, __half* __restrict__ wqkvT) {
    int z = blockIdx.z;
    int tx = threadIdx.x, ty = threadIdx.y;  // 32 x 8
    if (z == 3) {
        int lb = blockIdx.y * 64 + blockIdx.x;
        if (lb >= 3072) return;
        int i = lb * 256 + ty * 32 + tx;
        int n = i >> 9;
        int d = i & 511;
        int sel = n >> 9;
        int nn = n & 511;
        int h = nn >> 6, kk = nn & 63;
        const float* w = (sel == 0) ? wq : (sel == 1) ? wk : wv;
        wqkvT[i] = __float2half_rn(w[(h * DM + d) * DK + kk]);
        return;
    }
    __shared__ float t[32][33];
    const float* in;
    __half* out;
    int R, C;
    if (z == 0)      { in = proj_w; out = projwT; R = DM;     C = DM; }
    else if (z == 1) { in = w1;     out = w1T;    R = DM;     C = DINNER; }
    else             { in = w2;     out = w2T;    R = DINNER; C = DM; }
    int c0 = blockIdx.x * 32, r0 = blockIdx.y * 32;
    if (c0 >= C || r0 >= R) return;
#pragma unroll
    for (int j = 0; j < 32; j += 8)
        t[ty + j][tx] = in[(size_t)(r0 + ty + j) * C + c0 + tx];
    __syncthreads();
#pragma unroll
    for (int j = 0; j < 32; j += 8)
        out[(size_t)(c0 + ty + j) * R + r0 + tx] = __float2half_rn(t[tx][ty + j]);
}

// ---------------- skipper ----------------
__global__ void skipper_scan(const int* __restrict__ keep, int* __restrict__ idx,
                             int* __restrict__ nkeep) {
    int b = blockIdx.x, t = threadIdx.x;
    __shared__ int sh[SS];
    int v = keep[b * SS + t] > 0;
    sh[t] = v;
    __syncthreads();
    for (int off = 1; off < SS; off <<= 1) {
        int x = (t >= off) ? sh[t - off] : 0;
        __syncthreads();
        sh[t] += x;
        __syncthreads();
    }
    int incl = sh[t];
    if (v) idx[b * SS + incl - 1] = t;
    if (t == SS - 1) nkeep[b] = incl;
}

// 2 rows per 256-thread block
__global__ void gather_kernel(const float* __restrict__ x, const int* __restrict__ idx,
                              const int* __restrict__ nkeep, __half* __restrict__ xch) {
    int bs = blockIdx.x * 2 + (threadIdx.x >> 7);
    int t = threadIdx.x & 127;
    int b = bs >> 9, s = bs & 511;
    int nk = nkeep[b];
    float4 v = make_float4(0.f, 0.f, 0.f, 0.f);
    if (s < nk)
        v = ((const float4*)(x + ((size_t)b * SS + idx[b * SS + s]) * DM))[t];
    __half2 h0 = __floats2half2_rn(v.x, v.y);
    __half2 h1 = __floats2half2_rn(v.z, v.w);
    uint2 u;
    u.x = *(uint32_t*)&h0;
    u.y = *(uint32_t*)&h1;
    ((uint2*)(xch + (size_t)bs * DM))[t] = u;
}

// ---------------- fp16 tensor-core GEMM (128x128 tile, BK=64, 3-stage) ----------------
// nkeep != null (QKV only): M-tiles whose batch-local start >= nk are all-zero ->
// skip mainloop, zero-fill output.
#define HSM_TOTAL 98304   // 3 x (16K A + 16K B)

__global__ void __launch_bounds__(256, 2) hgemm(
    const __half* __restrict__ A, const __half* __restrict__ Bt,
    float* __restrict__ Cf, __half* __restrict__ Ch,
    int M, int N, int K, const float* __restrict__ bias, int relu,
    const int* __restrict__ nkeep) {
    extern __shared__ __align__(128) char smc[];
    uint32_t sbase = smem_u32(smc);     // A bufs: 0..49152, B bufs: 49152..98304

    int tid = threadIdx.x;
    int wid = tid >> 5, lane = tid & 31;
    int g = lane >> 2, t4 = lane & 3;
    int l15 = lane & 15, l16 = lane >> 4;
    int wm = wid >> 2, wn = wid & 3;
    int rowBase = blockIdx.y * 128;
    int colBase = blockIdx.x * 128;

    // zero-row M-tile skip (QKV path): whole tile beyond this batch's kept rows
    if (nkeep) {
        int nk = nkeep[rowBase >> 9];
        if ((rowBase & 511) >= nk) {
#pragma unroll
            for (int mt = 0; mt < 4; mt++) {
                int r0 = rowBase + wm * 64 + mt * 16 + g;
#pragma unroll
                for (int nt = 0; nt < 4; nt++) {
                    int c = colBase + wn * 32 + nt * 8 + 2 * t4;
                    if (Ch) {
                        *(uint32_t*)(Ch + (size_t)r0 * N + c) = 0u;
                        *(uint32_t*)(Ch + (size_t)(r0 + 8) * N + c) = 0u;
                    }
                    if (Cf) {
                        *(float2*)(Cf + (size_t)r0 * N + c) = make_float2(0.f, 0.f);
                        *(float2*)(Cf + (size_t)(r0 + 8) * N + c) = make_float2(0.f, 0.f);
                    }
                }
            }
            return;
        }
    }

    float acc[4][4][4];
#pragma unroll
    for (int i = 0; i < 4; i++)
#pragma unroll
        for (int j = 0; j < 4; j++)
#pragma unroll
            for (int c = 0; c < 4; c++) acc[i][j][c] = 0.f;

    const int nc = K / 64;

    auto load_tile = [&](int kt, int buf) {
        int k0 = kt * 64;
#pragma unroll
        for (int j = 0; j < 4; j++) {
            int cid = tid + 256 * j;
            int row = cid >> 3, c = cid & 7;
            uint32_t off = row * 128 + ((c ^ (row & 7)) << 4);
            cpa16(sbase + buf * 16384 + off,
                  A + (size_t)(rowBase + row) * K + k0 + c * 8);
            cpa16(sbase + 49152 + buf * 16384 + off,
                  Bt + (size_t)(colBase + row) * K + k0 + c * 8);
        }
        asm volatile("cp.async.commit_group;");
    };

    load_tile(0, 0);
    if (nc > 1) load_tile(1, 1);

    for (int kt = 0; kt < nc; kt++) {
        int buf = kt % 3;
        if (kt + 2 < nc) {
            load_tile(kt + 2, (kt + 2) % 3);
            asm volatile("cp.async.wait_group 2;");
        } else if (kt + 1 < nc) {
            asm volatile("cp.async.wait_group 1;");
        } else {
            asm volatile("cp.async.wait_group 0;");
        }
        __syncthreads();

        uint32_t aBase = sbase + buf * 16384;
        uint32_t bBase = sbase + 49152 + buf * 16384;
#pragma unroll
        for (int ks = 0; ks < 4; ks++) {
            int ch = 2 * ks + l16;
            uint32_t a[4][4];
#pragma unroll
            for (int mt = 0; mt < 4; mt++) {
                int row = wm * 64 + mt * 16 + l15;
                ldm_x4(a[mt], aBase + row * 128 + ((ch ^ (row & 7)) << 4));
            }
            uint32_t bq[2][4];
#pragma unroll
            for (int bt = 0; bt < 2; bt++) {
                int row = wn * 32 + bt * 16 + l15;
                ldm_x4(bq[bt], bBase + row * 128 + ((ch ^ (row & 7)) << 4));
            }
#pragma unroll
            for (int mt = 0; mt < 4; mt++)
#pragma unroll
                for (int nt = 0; nt < 4; nt++)
                    mma_f16(acc[mt][nt], a[mt], bq[nt >> 1][nt & 1], bq[nt >> 1][2 + (nt & 1)]);
        }
        __syncthreads();
    }

#pragma unroll
    for (int mt = 0; mt < 4; mt++) {
        int r0 = rowBase + wm * 64 + mt * 16 + g;
#pragma unroll
        for (int nt = 0; nt < 4; nt++) {
            int c = colBase + wn * 32 + nt * 8 + 2 * t4;
            float b0 = bias ? __ldg(bias + c) : 0.f;
            float b1 = bias ? __ldg(bias + c + 1) : 0.f;
            float v0 = acc[mt][nt][0] + b0, v1 = acc[mt][nt][1] + b1;
            float v2 = acc[mt][nt][2] + b0, v3 = acc[mt][nt][3] + b1;
            if (relu) {
                v0 = fmaxf(v0, 0.f); v1 = fmaxf(v1, 0.f);
                v2 = fmaxf(v2, 0.f); v3 = fmaxf(v3, 0.f);
            }
            if (Cf) {
                *(float2*)(Cf + (size_t)r0 * N + c) = make_float2(v0, v1);
                *(float2*)(Cf + (size_t)(r0 + 8) * N + c) = make_float2(v2, v3);
            }
            if (Ch) {
                *(__half2*)(Ch + (size_t)r0 * N + c) = __floats2half2_rn(v0, v1);
                *(__half2*)(Ch + (size_t)(r0 + 8) * N + c) = __floats2half2_rn(v2, v3);
            }
        }
    }
}

// ---------------- fp16 tensor-core attention (masked-chunk skipping) ----------------
// block = (b,h) x 64-row s-tile, 256 threads / 8 warps, 2 CTA/SM.
// smem (halves strides): Q[64][72], KV[128][72], Es[64][520] fp16, ssum[64] fp32
#define SQ_OFF 0
#define SKV_OFF 9216
#define SE_OFF 27648
#define SSUM_OFF 94208
#define ATT_SMEM 94464

__global__ void __launch_bounds__(256, 2) attention_h(
    const __half* __restrict__ qkv, const int* __restrict__ nkeep,
    float* __restrict__ attns, __half* __restrict__ heads) {
    extern __shared__ __align__(128) char smc[];
    uint32_t sbase = smem_u32(smc);
    uint32_t sQ = sbase + SQ_OFF;
    uint32_t sKV = sbase + SKV_OFF;
    uint32_t sE = sbase + SE_OFF;
    float* ssum = (float*)(smc + SSUM_OFF);
    __half* EsH = (__half*)(smc + SE_OFF);

    int bh = blockIdx.x;
    int b = bh >> 3, h = bh & 7;
    int s0 = blockIdx.y * 64;
    int tid = threadIdx.x;
    int wid = tid >> 5, lane = tid & 31;
    int g = lane >> 2, t4 = lane & 3;
    int l15 = lane & 15, l16 = lane >> 4;
    int nk = nkeep[b];
    int kc = (nk + 127) >> 7;               // chunks of keys to actually compute
    if (kc < 1) kc = 1;
    if (kc > 4) kc = 4;
    const float sc = 0.04419417382415922f;  // 1/sqrt(512)
    const int QS = 3 * DM;                  // 1536 halves per row

    if (tid < 64) ssum[tid] = 0.f;

    // async-load Q tile (64 rows x 64 halves)
#pragma unroll
    for (int j = 0; j < 2; j++) {
        int cid = tid + 256 * j;
        int row = cid >> 3, c = cid & 7;
        cpa16(sQ + row * 144 + c * 16,
              qkv + ((size_t)(b * SS + s0 + row)) * QS + h * 64 + c * 8);
    }
    // async-load K chunk 0 (128 rows x 64 halves)
#pragma unroll
    for (int j = 0; j < 4; j++) {
        int cid = tid + 256 * j;
        int row = cid >> 3, c = cid & 7;
        cpa16(sKV + row * 144 + c * 16,
              qkv + ((size_t)(b * SS + row)) * QS + 512 + h * 64 + c * 8);
    }
    asm volatile("cp.async.commit_group;");

    // fully-masked attns chunks: write zeros now (overlaps the initial loads)
    float* attn_base = attns + (((size_t)(h * BB + b)) * SS + s0) * SS;
    for (int ci = kc; ci < 4; ci++) {
        int t0c = ci * 128;
        for (int i = tid; i < 2048; i += 256) {
            int row = i >> 5, c4 = (i & 31) * 4;
            stcs4(attn_base + (size_t)row * SS + t0c + c4, make_float4(0.f, 0.f, 0.f, 0.f));
        }
    }

    asm volatile("cp.async.wait_group 0;");
    __syncthreads();

    // ---- Phase A: exp(QK^T * sc) -> Es fp16 for kc chunks only ----
    int wmA = wid >> 2, wnA = wid & 3;  // 2 x 4; warp tile m32 x n32
    float psum[4] = {0.f, 0.f, 0.f, 0.f};
    int lim = kc * 128;

    for (int t0 = 0; t0 < lim; t0 += 128) {
        float acc[2][4][4];
#pragma unroll
        for (int i = 0; i < 2; i++)
#pragma unroll
            for (int j = 0; j < 4; j++)
#pragma unroll
                for (int c = 0; c < 4; c++) acc[i][j][c] = 0.f;

#pragma unroll
        for (int ks = 0; ks < 4; ks++) {
            uint32_t a[2][4];
#pragma unroll
            for (int mt = 0; mt < 2; mt++) {
                int row = wmA * 32 + mt * 16 + l15;
                ldm_x4(a[mt], sQ + row * 144 + ks * 32 + l16 * 16);
            }
            uint32_t bq[2][4];
#pragma unroll
            for (int bt = 0; bt < 2; bt++) {
                int row = wnA * 32 + bt * 16 + l15;
                ldm_x4(bq[bt], sKV + row * 144 + ks * 32 + l16 * 16);
            }
#pragma unroll
            for (int mt = 0; mt < 2; mt++)
#pragma unroll
                for (int nt = 0; nt < 4; nt++)
                    mma_f16(acc[mt][nt], a[mt], bq[nt >> 1][nt & 1], bq[nt >> 1][2 + (nt & 1)]);
        }
        __syncthreads();  // done reading K chunk

        // prefetch next K chunk
        if (t0 + 128 < lim) {
#pragma unroll
            for (int j = 0; j < 4; j++) {
                int cid = tid + 256 * j;
                int row = cid >> 3, c = cid & 7;
                cpa16(sKV + row * 144 + c * 16,
                      qkv + ((size_t)(b * SS + t0 + 128 + row)) * QS + 512 + h * 64 + c * 8);
            }
            asm volatile("cp.async.commit_group;");
        }

        // exp + mask + store fp16 + accumulate partial row sums
#pragma unroll
        for (int mt = 0; mt < 2; mt++) {
            int r0 = wmA * 32 + mt * 16 + g;
#pragma unroll
            for (int nt = 0; nt < 4; nt++) {
                int col = t0 + wnA * 32 + nt * 8 + 2 * t4;
                float e0 = (col     < nk) ? fast_exp(acc[mt][nt][0] * sc) : 0.f;
                float e1 = (col + 1 < nk) ? fast_exp(acc[mt][nt][1] * sc) : 0.f;
                float e2 = (col     < nk) ? fast_exp(acc[mt][nt][2] * sc) : 0.f;
                float e3 = (col + 1 < nk) ? fast_exp(acc[mt][nt][3] * sc) : 0.f;
                *(__half2*)(EsH + r0 * 520 + col) = __floats2half2_rn(e0, e1);
                *(__half2*)(EsH + (r0 + 8) * 520 + col) = __floats2half2_rn(e2, e3);
                psum[mt * 2 + 0] += e0 + e1;
                psum[mt * 2 + 1] += e2 + e3;
            }
        }

        if (t0 + 128 < lim) {
            asm volatile("cp.async.wait_group 0;");
            __syncthreads();
        }
    }

    // merge partial sums
#pragma unroll
    for (int mt = 0; mt < 2; mt++) {
        atomicAdd(&ssum[wmA * 32 + mt * 16 + g], psum[mt * 2 + 0]);
        atomicAdd(&ssum[wmA * 32 + mt * 16 + g + 8], psum[mt * 2 + 1]);
    }
    __syncthreads();
    if (tid < 64) ssum[tid] = 1.f / ssum[tid];
    __syncthreads();

    // normalized-P chunk writer (reads Es)
    auto write_chunk = [&](int t0) {
        for (int i = tid; i < 2048; i += 256) {
            int row = i >> 5, c4 = (i & 31) * 4;
            uint2 u = *(uint2*)(EsH + row * 520 + t0 + c4);
            float2 f0 = __half22float2(*(__half2*)&u.x);
            float2 f1 = __half22float2(*(__half2*)&u.y);
            float riv = ssum[row];
            stcs4(attn_base + (size_t)row * SS + t0 + c4,
                  make_float4(f0.x * riv, f0.y * riv, f1.x * riv, f1.y * riv));
        }
    };

    // prefetch V chunk 0; overlap with attns chunk-0 write
#pragma unroll
    for (int j = 0; j < 4; j++) {
        int cid = tid + 256 * j;
        int row = cid >> 3, c = cid & 7;
        cpa16(sKV + row * 144 + c * 16,
              qkv + ((size_t)(b * SS + row)) * QS + 1024 + h * 64 + c * 8);
    }
    asm volatile("cp.async.commit_group;");
    write_chunk(0);
    asm volatile("cp.async.wait_group 0;");
    __syncthreads();

    // ---- Phase B: O = (Es @ V) * rinv over kc chunks, attns writes interleaved ----
    int wmB = wid >> 1, wnB = wid & 1;  // 4 x 2; warp tile m16 x n32
    float oacc[4][4];
#pragma unroll
    for (int j = 0; j < 4; j++)
#pragma unroll
        for (int c = 0; c < 4; c++) oacc[j][c] = 0.f;

    for (int ci = 0; ci < kc; ci++) {
        int t0 = ci * 128;
#pragma unroll
        for (int k16 = 0; k16 < 8; k16++) {
            uint32_t a[4];
            {
                int row = wmB * 16 + l15;
                ldm_x4(a, sE + row * 1040 + (t0 + k16 * 16) * 2 + l16 * 16);
            }
            uint32_t bt[2][4];
#pragma unroll
            for (int pair = 0; pair < 2; pair++) {
                int kr = k16 * 16 + l15;
                int nv = wnB * 32 + pair * 16 + l16 * 8;
                ldm_x4_t(bt[pair], sKV + kr * 144 + nv * 2);
            }
            // trans-ldmatrix register order: {b0(n-low), b1(n-low), b0(n-high), b1(n-high)}
#pragma unroll
            for (int nt = 0; nt < 4; nt++)
                mma_f16(oacc[nt], a, bt[nt >> 1][(nt & 1) * 2], bt[nt >> 1][(nt & 1) * 2 + 1]);
        }
        __syncthreads();
        if (ci + 1 < kc) {
            // prefetch next V chunk, then hide attns store of chunk ci+1 under it
#pragma unroll
            for (int j = 0; j < 4; j++) {
                int cid = tid + 256 * j;
                int row = cid >> 3, c = cid & 7;
                cpa16(sKV + row * 144 + c * 16,
                      qkv + ((size_t)(b * SS + t0 + 128 + row)) * QS + 1024 + h * 64 + c * 8);
            }
            asm volatile("cp.async.commit_group;");
            write_chunk(t0 + 128);
            asm volatile("cp.async.wait_group 0;");
            __syncthreads();
        }
    }

    // write O (fp16 heads)
    {
        int r0 = wmB * 16 + g;
        float ri0 = ssum[r0], ri1 = ssum[r0 + 8];
        size_t base0 = ((size_t)(b * SS + s0 + r0)) * DM + h * 64;
        size_t base1 = ((size_t)(b * SS + s0 + r0 + 8)) * DM + h * 64;
#pragma unroll
        for (int nt = 0; nt < 4; nt++) {
            int c = wnB * 32 + nt * 8 + 2 * t4;
            *(__half2*)(heads + base0 + c) =
                __floats2half2_rn(oacc[nt][0] * ri0, oacc[nt][1] * ri0);
            *(__half2*)(heads + base1 + c) =
                __floats2half2_rn(oacc[nt][2] * ri1, oacc[nt][3] * ri1);
        }
    }
}

// ---------------- layernorm (fp16 in, fp32 math): out_f and/or out_h ----------------
__global__ void ln_kernel(const __half* __restrict__ y, const __half* __restrict__ resid,
                          const float* __restrict__ g, const float* __restrict__ be,
                          float* __restrict__ out_f, __half* __restrict__ out_h) {
    int row = blockIdx.x;
    int tid = threadIdx.x;  // 128
    uint2 uy = ((const uint2*)(y + (size_t)row * DM))[tid];
    uint2 ur = ((const uint2*)(resid + (size_t)row * DM))[tid];
    float2 a0 = __half22float2(*(__half2*)&uy.x);
    float2 a1 = __half22float2(*(__half2*)&uy.y);
    float2 b0 = __half22float2(*(__half2*)&ur.x);
    float2 b1 = __half22float2(*(__half2*)&ur.y);
    float v0 = a0.x + b0.x, v1 = a0.y + b0.y, v2 = a1.x + b1.x, v3 = a1.y + b1.y;
    float s = v0 + v1 + v2 + v3;
    float ss = v0 * v0 + v1 * v1 + v2 * v2 + v3 * v3;
    for (int o = 16; o; o >>= 1) {
        s += __shfl_xor_sync(~0u, s, o);
        ss += __shfl_xor_sync(~0u, ss, o);
    }
    __shared__ float shs[4], shss[4];
    int w = tid >> 5, l = tid & 31;
    if (l == 0) { shs[w] = s; shss[w] = ss; }
    __syncthreads();
    s = shs[0] + shs[1] + shs[2] + shs[3];
    ss = shss[0] + shss[1] + shss[2] + shss[3];
    float mu = s * (1.f / 512.f);
    float var = fmaxf((ss - 512.f * mu * mu) * (1.f / 511.f), 0.f);
    float inv = 1.f / (sqrtf(var) + EPSLN);
    float4 gg = ((const float4*)g)[tid];
    float4 bb = ((const float4*)be)[tid];
    float o0 = (v0 - mu) * inv * gg.x + bb.x;
    float o1 = (v1 - mu) * inv * gg.y + bb.y;
    float o2 = (v2 - mu) * inv * gg.z + bb.z;
    float o3 = (v3 - mu) * inv * gg.w + bb.w;
    if (out_f)
        stcs4(out_f + (size_t)row * DM + tid * 4, make_float4(o0, o1, o2, o3));
    if (out_h) {
        __half2 h0 = __floats2half2_rn(o0, o1);
        __half2 h1 = __floats2half2_rn(o2, o3);
        uint2 u;
        u.x = *(uint32_t*)&h0;
        u.y = *(uint32_t*)&h1;
        ((uint2*)(out_h + (size_t)row * DM))[tid] = u;
    }
}

// ---------------- launch ----------------
extern "C" void kernel_launch(void* const* d_in, const int* in_sizes, int n_in,
                              void* d_out, int out_size) {
    const float* x      = (const float*)d_in[0];
    const float* w_qs   = (const float*)d_in[1];
    const float* w_ks   = (const float*)d_in[2];
    const float* w_vs   = (const float*)d_in[3];
    const float* proj_w = (const float*)d_in[4];
    const float* proj_b = (const float*)d_in[5];
    const float* ln1_g  = (const float*)d_in[6];
    const float* ln1_b  = (const float*)d_in[7];
    const float* ffn_w1 = (const float*)d_in[8];
    const float* ffn_b1 = (const float*)d_in[9];
    const float* ffn_w2 = (const float*)d_in[10];
    const float* ffn_b2 = (const float*)d_in[11];
    const float* ln2_g  = (const float*)d_in[12];
    const float* ln2_b  = (const float*)d_in[13];
    const int*   keepm  = (const int*)d_in[14];

    float* out = (float*)d_out;
    float* enc_out = out;
    float* attns   = out + ENC_ELEMS;

    __half *xch, *qkvh, *headsh, *tmph, *attnouth, *ffnh, *wqkvT, *projwT, *w1T, *w2T;
    int *idx, *nk;
    cudaGetSymbolAddress((void**)&xch, g_xch);
    cudaGetSymbolAddress((void**)&qkvh, g_qkvh);
    cudaGetSymbolAddress((void**)&headsh, g_headsh);
    cudaGetSymbolAddress((void**)&tmph, g_tmph);
    cudaGetSymbolAddress((void**)&attnouth, g_attnouth);
    cudaGetSymbolAddress((void**)&ffnh, g_ffnh);
    cudaGetSymbolAddress((void**)&wqkvT, g_wqkvT);
    cudaGetSymbolAddress((void**)&projwT, g_projwT);
    cudaGetSymbolAddress((void**)&w1T, g_w1T);
    cudaGetSymbolAddress((void**)&w2T, g_w2T);
    cudaGetSymbolAddress((void**)&idx, g_idx);
    cudaGetSymbolAddress((void**)&nk, g_nkeep);

    static int smem_set = 0;
    if (!smem_set) {
        cudaFuncSetAttribute(attention_h, cudaFuncAttributeMaxDynamicSharedMemorySize, ATT_SMEM);
        cudaFuncSetAttribute(hgemm, cudaFuncAttributeMaxDynamicSharedMemorySize, HSM_TOTAL);
        smem_set = 1;
    }

    // 0: all weight prep (3 transposes + qkv pack) in one launch
    prep_all<<<dim3(64, 64, 4), dim3(32, 8)>>>(proj_w, ffn_w1, ffn_w2, w_qs, w_ks, w_vs,
                                               projwT, w1T, w2T, wqkvT);
    // 1: skipper
    skipper_scan<<<BB, SS>>>(keepm, idx, nk);
    // 2: gather (fp16 only)
    gather_kernel<<<MTOT / 2, 256>>>(x, idx, nk, xch);
    // 3: fused QKV projection -> fp16 qkv (zero-row tile skip via nk)
    hgemm<<<dim3(1536 / 128, MTOT / 128), 256, HSM_TOTAL>>>(
        xch, wqkvT, nullptr, qkvh, MTOT, 1536, DM, nullptr, 0, nk);
    // 4: fp16 attention (writes attns fp32 + heads fp16)
    attention_h<<<dim3(BB * NH, SS / 64), 256, ATT_SMEM>>>(qkvh, nk, attns, headsh);
    // 5: output projection (fp16 out)
    hgemm<<<dim3(DM / 128, MTOT / 128), 256, HSM_TOTAL>>>(
        headsh, projwT, nullptr, tmph, MTOT, DM, DM, proj_b, 0, nullptr);
    // 6: LN1 (fp16 out only)
    ln_kernel<<<MTOT, 128>>>(tmph, xch, ln1_g, ln1_b, nullptr, attnouth);
    // 7: FFN1 (relu, fp16 out)
    hgemm<<<dim3(DINNER / 128, MTOT / 128), 256, HSM_TOTAL>>>(
        attnouth, w1T, nullptr, ffnh, MTOT, DINNER, DM, ffn_b1, 1, nullptr);
    // 8: FFN2 (fp16 out)
    hgemm<<<dim3(DM / 128, MTOT / 128), 256, HSM_TOTAL>>>(
        ffnh, w2T, nullptr, tmph, MTOT, DM, DINNER, ffn_b2, 0, nullptr);
    // 9: LN2 -> enc_out fp32
    ln_kernel<<<MTOT, 128>>>(tmph, attnouth, ln2_g, ln2_b, enc_out, nullptr);
}